// round 10
// baseline (speedup 1.0000x reference)
#include <cuda_runtime.h>
#include <cuda_bf16.h>
#include <cstdint>

// out[m,e] = sum_f relu( sum_e' cos(x[m,e'])*cos(theta[e']) * W1[f,e'] ) * W2[e,f]
// M = 131072, E = 128, F = 512.
//
// R6: 512 threads / 16 warps per CTA (was 256/8). Same BM=128 tile, same
// tf32 mma.sync path; warp grid 8m x 2n. Doubles mma issue parallelism at
// unchanged smem footprint (1 CTA/SM), halves register pressure.

#define THREADS 512
#define BM      128
#define EDIM    128
#define FDIM    512
#define CF      64
#define NCHUNK  (FDIM / CF)

// smem row strides in floats (pad +4 -> stride mod 32 == 4 -> conflict-free frags)
#define QS  132
#define HS  68
#define W1S 132
#define W2S 68

#define OFF_Q  0
#define OFF_H  (OFF_Q  + BM * QS)    // 16896
#define OFF_W1 (OFF_H  + BM * HS)    // 25600
#define OFF_W2 (OFF_W1 + CF * W1S)   // 34048
#define OFF_CT (OFF_W2 + EDIM * W2S) // 42752
#define SMEM_FLOATS (OFF_CT + EDIM)  // 42880
#define SMEM_BYTES  (SMEM_FLOATS * 4) // 171520

__device__ __forceinline__ float tf32r(float v) {
    asm("cvt.rna.tf32.f32 %0, %0;" : "+f"(v));
    return v;
}

__device__ __forceinline__ void mma8(float* acc,
                                     uint32_t a0, uint32_t a1, uint32_t a2, uint32_t a3,
                                     uint32_t b0, uint32_t b1) {
    asm volatile(
        "mma.sync.aligned.m16n8k8.row.col.f32.tf32.tf32.f32 "
        "{%0,%1,%2,%3}, {%4,%5,%6,%7}, {%8,%9}, {%0,%1,%2,%3};"
        : "+f"(acc[0]), "+f"(acc[1]), "+f"(acc[2]), "+f"(acc[3])
        : "r"(a0), "r"(a1), "r"(a2), "r"(a3), "r"(b0), "r"(b1));
}

__global__ void __launch_bounds__(THREADS, 1)
ffq_kernel(const float* __restrict__ x,
           const float* __restrict__ theta,
           const float* __restrict__ W1,
           const float* __restrict__ W2,
           float* __restrict__ out) {
    extern __shared__ float s[];
    float* sq  = s + OFF_Q;   // [BM][QS]  q tile (tf32-rounded)
    float* sh  = s + OFF_H;   // [BM][HS]  relu(h) chunk (tf32-rounded)
    float* sw1 = s + OFF_W1;  // [CF][W1S] W1 chunk, rows=f_local, cols=e
    float* sw2 = s + OFF_W2;  // [E][W2S]  W2 chunk, rows=e, cols=f_local
    float* sct = s + OFF_CT;  // [E] cos(theta)

    const int tid  = threadIdx.x;
    const int warp = tid >> 5;
    const int lane = tid & 31;
    const int gid  = lane >> 2;   // group id (0..7)
    const int t4   = lane & 3;    // thread-in-group (0..3)
    const int wm   = warp >> 1;   // 0..7  -> m base (16-row tiles)
    const int wn   = warp & 1;    // 0..1
    const int m0   = 16 * wm;
    const int n0f  = 32 * wn;     // phase-1 f_local base (warp tile 16x32)
    const int n0e  = 64 * wn;     // phase-2 e base       (warp tile 16x64)

    if (tid < EDIM) sct[tid] = cosf(theta[tid]);
    __syncthreads();

    // ---- q tile: load x block, q = cos(x)*cos(theta), round to tf32 ----
    {
        const float4* xg = (const float4*)(x + (size_t)blockIdx.x * (BM * EDIM));
        #pragma unroll
        for (int i = tid; i < BM * EDIM / 4; i += THREADS) {   // 4096 float4
            const int row = i >> 5;         // 32 float4 per row
            const int col = (i & 31) * 4;
            float4 v = xg[i];
            float4 q;
            q.x = tf32r(cosf(v.x) * sct[col + 0]);
            q.y = tf32r(cosf(v.y) * sct[col + 1]);
            q.z = tf32r(cosf(v.z) * sct[col + 2]);
            q.w = tf32r(cosf(v.w) * sct[col + 3]);
            *(float4*)&sq[row * QS + col] = q;
        }
    }

    float oacc[8][4];
    #pragma unroll
    for (int ni = 0; ni < 8; ni++)
        #pragma unroll
        for (int r = 0; r < 4; r++) oacc[ni][r] = 0.f;

    for (int c = 0; c < NCHUNK; c++) {
        // ---- load W1 chunk [CF=64 rows f][128 e] and W2 chunk [128 e][CF f] ----
        {
            const float4* w1g = (const float4*)(W1 + (size_t)c * CF * EDIM);
            #pragma unroll
            for (int i = tid; i < CF * (EDIM / 4); i += THREADS) {  // 2048 float4
                const int r = i >> 5, col = (i & 31) * 4;
                float4 v = w1g[i];
                v.x = tf32r(v.x); v.y = tf32r(v.y); v.z = tf32r(v.z); v.w = tf32r(v.w);
                *(float4*)&sw1[r * W1S + col] = v;
            }
            #pragma unroll
            for (int i = tid; i < EDIM * (CF / 4); i += THREADS) {  // 2048 float4
                const int r = i >> 4, col = (i & 15) * 4;
                float4 v = *(const float4*)(W2 + (size_t)r * FDIM + c * CF + col);
                v.x = tf32r(v.x); v.y = tf32r(v.y); v.z = tf32r(v.z); v.w = tf32r(v.w);
                *(float4*)&sw2[r * W2S + col] = v;
            }
        }
        __syncthreads();   // q + weight tiles ready (also guards prev-iter smem reuse)

        // ---- phase 1: h = q @ W1_c^T   (warp tile 16m x 32f) ----
        float hacc[4][4];
        #pragma unroll
        for (int ni = 0; ni < 4; ni++)
            #pragma unroll
            for (int r = 0; r < 4; r++) hacc[ni][r] = 0.f;

        #pragma unroll
        for (int k = 0; k < EDIM; k += 8) {
            const float* qb = &sq[(m0 + gid) * QS + k + t4];
            const uint32_t a0 = __float_as_uint(qb[0]);
            const uint32_t a2 = __float_as_uint(qb[4]);
            const uint32_t a1 = __float_as_uint(qb[8 * QS]);
            const uint32_t a3 = __float_as_uint(qb[8 * QS + 4]);
            #pragma unroll
            for (int ni = 0; ni < 4; ni++) {
                const float* wb = &sw1[(n0f + 8 * ni + gid) * W1S + k + t4];
                const uint32_t b0 = __float_as_uint(wb[0]);
                const uint32_t b1 = __float_as_uint(wb[4]);
                mma8(hacc[ni], a0, a1, a2, a3, b0, b1);
            }
        }

        // relu + tf32 round + store h chunk to smem
        #pragma unroll
        for (int ni = 0; ni < 4; ni++) {
            const int row = m0 + gid;
            const int col = n0f + 8 * ni + 2 * t4;
            float2 v0;
            v0.x = tf32r(fmaxf(hacc[ni][0], 0.f));
            v0.y = tf32r(fmaxf(hacc[ni][1], 0.f));
            *(float2*)&sh[row * HS + col] = v0;
            float2 v1;
            v1.x = tf32r(fmaxf(hacc[ni][2], 0.f));
            v1.y = tf32r(fmaxf(hacc[ni][3], 0.f));
            *(float2*)&sh[(row + 8) * HS + col] = v1;
        }
        __syncthreads();   // h chunk visible to all warps

        // ---- phase 2: out += h_c @ W2_c^T   (warp tile 16m x 64e) ----
        #pragma unroll
        for (int k = 0; k < CF; k += 8) {
            const float* hb = &sh[(m0 + gid) * HS + k + t4];
            const uint32_t a0 = __float_as_uint(hb[0]);
            const uint32_t a2 = __float_as_uint(hb[4]);
            const uint32_t a1 = __float_as_uint(hb[8 * HS]);
            const uint32_t a3 = __float_as_uint(hb[8 * HS + 4]);
            #pragma unroll
            for (int ni = 0; ni < 8; ni++) {
                const float* wb = &sw2[(n0e + 8 * ni + gid) * W2S + k + t4];
                const uint32_t b0 = __float_as_uint(wb[0]);
                const uint32_t b1 = __float_as_uint(wb[4]);
                mma8(oacc[ni], a0, a1, a2, a3, b0, b1);
            }
        }
        __syncthreads();   // done with h / w tiles before next chunk overwrites
    }

    // ---- epilogue: write out tile (fp32) ----
    float* ob = out + (size_t)blockIdx.x * BM * EDIM;
    #pragma unroll
    for (int ni = 0; ni < 8; ni++) {
        const int row = m0 + gid;
        const int col = n0e + 8 * ni + 2 * t4;
        float2 v0 = make_float2(oacc[ni][0], oacc[ni][1]);
        float2 v1 = make_float2(oacc[ni][2], oacc[ni][3]);
        *(float2*)&ob[row * EDIM + col]       = v0;
        *(float2*)&ob[(row + 8) * EDIM + col] = v1;
    }
}

extern "C" void kernel_launch(void* const* d_in, const int* in_sizes, int n_in,
                              void* d_out, int out_size) {
    const float* x     = (const float*)d_in[0];
    const float* theta = (const float*)d_in[1];
    const float* W1    = (const float*)d_in[2];
    const float* W2    = (const float*)d_in[3];
    float* out = (float*)d_out;

    const int rows = in_sizes[0] / EDIM;   // 131072
    const int grid = rows / BM;            // 1024

    cudaFuncSetAttribute(ffq_kernel, cudaFuncAttributeMaxDynamicSharedMemorySize,
                         SMEM_BYTES);
    ffq_kernel<<<grid, THREADS, SMEM_BYTES>>>(x, theta, W1, W2, out);
}

// round 11
// speedup vs baseline: 1.0018x; 1.0018x over previous
#include <cuda_runtime.h>
#include <cuda_bf16.h>
#include <cstdint>

// out[m,e] = sum_f relu( sum_e' cos(x[m,e'])*cos(theta[e']) * W1[f,e'] ) * W2[e,f]
// M = 131072, E = 128, F = 512.
//
// R6: 512 threads / 16 warps per CTA (was 256/8). Same BM=128 tile, same
// tf32 mma.sync path; warp grid 8m x 2n. Doubles mma issue parallelism at
// unchanged smem footprint (1 CTA/SM), halves register pressure.

#define THREADS 512
#define BM      128
#define EDIM    128
#define FDIM    512
#define CF      64
#define NCHUNK  (FDIM / CF)

// smem row strides in floats (pad +4 -> stride mod 32 == 4 -> conflict-free frags)
#define QS  132
#define HS  68
#define W1S 132
#define W2S 68

#define OFF_Q  0
#define OFF_H  (OFF_Q  + BM * QS)    // 16896
#define OFF_W1 (OFF_H  + BM * HS)    // 25600
#define OFF_W2 (OFF_W1 + CF * W1S)   // 34048
#define OFF_CT (OFF_W2 + EDIM * W2S) // 42752
#define SMEM_FLOATS (OFF_CT + EDIM)  // 42880
#define SMEM_BYTES  (SMEM_FLOATS * 4) // 171520

__device__ __forceinline__ float tf32r(float v) {
    asm("cvt.rna.tf32.f32 %0, %0;" : "+f"(v));
    return v;
}

__device__ __forceinline__ void mma8(float* acc,
                                     uint32_t a0, uint32_t a1, uint32_t a2, uint32_t a3,
                                     uint32_t b0, uint32_t b1) {
    asm volatile(
        "mma.sync.aligned.m16n8k8.row.col.f32.tf32.tf32.f32 "
        "{%0,%1,%2,%3}, {%4,%5,%6,%7}, {%8,%9}, {%0,%1,%2,%3};"
        : "+f"(acc[0]), "+f"(acc[1]), "+f"(acc[2]), "+f"(acc[3])
        : "r"(a0), "r"(a1), "r"(a2), "r"(a3), "r"(b0), "r"(b1));
}

__global__ void __launch_bounds__(THREADS, 1)
ffq_kernel(const float* __restrict__ x,
           const float* __restrict__ theta,
           const float* __restrict__ W1,
           const float* __restrict__ W2,
           float* __restrict__ out) {
    extern __shared__ float s[];
    float* sq  = s + OFF_Q;   // [BM][QS]  q tile (tf32-rounded)
    float* sh  = s + OFF_H;   // [BM][HS]  relu(h) chunk (tf32-rounded)
    float* sw1 = s + OFF_W1;  // [CF][W1S] W1 chunk, rows=f_local, cols=e
    float* sw2 = s + OFF_W2;  // [E][W2S]  W2 chunk, rows=e, cols=f_local
    float* sct = s + OFF_CT;  // [E] cos(theta)

    const int tid  = threadIdx.x;
    const int warp = tid >> 5;
    const int lane = tid & 31;
    const int gid  = lane >> 2;   // group id (0..7)
    const int t4   = lane & 3;    // thread-in-group (0..3)
    const int wm   = warp >> 1;   // 0..7  -> m base (16-row tiles)
    const int wn   = warp & 1;    // 0..1
    const int m0   = 16 * wm;
    const int n0f  = 32 * wn;     // phase-1 f_local base (warp tile 16x32)
    const int n0e  = 64 * wn;     // phase-2 e base       (warp tile 16x64)

    if (tid < EDIM) sct[tid] = cosf(theta[tid]);
    __syncthreads();

    // ---- q tile: load x block, q = cos(x)*cos(theta), round to tf32 ----
    {
        const float4* xg = (const float4*)(x + (size_t)blockIdx.x * (BM * EDIM));
        #pragma unroll
        for (int i = tid; i < BM * EDIM / 4; i += THREADS) {   // 4096 float4
            const int row = i >> 5;         // 32 float4 per row
            const int col = (i & 31) * 4;
            float4 v = xg[i];
            float4 q;
            q.x = tf32r(cosf(v.x) * sct[col + 0]);
            q.y = tf32r(cosf(v.y) * sct[col + 1]);
            q.z = tf32r(cosf(v.z) * sct[col + 2]);
            q.w = tf32r(cosf(v.w) * sct[col + 3]);
            *(float4*)&sq[row * QS + col] = q;
        }
    }

    float oacc[8][4];
    #pragma unroll
    for (int ni = 0; ni < 8; ni++)
        #pragma unroll
        for (int r = 0; r < 4; r++) oacc[ni][r] = 0.f;

    for (int c = 0; c < NCHUNK; c++) {
        // ---- load W1 chunk [CF=64 rows f][128 e] and W2 chunk [128 e][CF f] ----
        {
            const float4* w1g = (const float4*)(W1 + (size_t)c * CF * EDIM);
            #pragma unroll
            for (int i = tid; i < CF * (EDIM / 4); i += THREADS) {  // 2048 float4
                const int r = i >> 5, col = (i & 31) * 4;
                float4 v = w1g[i];
                v.x = tf32r(v.x); v.y = tf32r(v.y); v.z = tf32r(v.z); v.w = tf32r(v.w);
                *(float4*)&sw1[r * W1S + col] = v;
            }
            #pragma unroll
            for (int i = tid; i < EDIM * (CF / 4); i += THREADS) {  // 2048 float4
                const int r = i >> 4, col = (i & 15) * 4;
                float4 v = *(const float4*)(W2 + (size_t)r * FDIM + c * CF + col);
                v.x = tf32r(v.x); v.y = tf32r(v.y); v.z = tf32r(v.z); v.w = tf32r(v.w);
                *(float4*)&sw2[r * W2S + col] = v;
            }
        }
        __syncthreads();   // q + weight tiles ready (also guards prev-iter smem reuse)

        // ---- phase 1: h = q @ W1_c^T   (warp tile 16m x 32f) ----
        float hacc[4][4];
        #pragma unroll
        for (int ni = 0; ni < 4; ni++)
            #pragma unroll
            for (int r = 0; r < 4; r++) hacc[ni][r] = 0.f;

        #pragma unroll
        for (int k = 0; k < EDIM; k += 8) {
            const float* qb = &sq[(m0 + gid) * QS + k + t4];
            const uint32_t a0 = __float_as_uint(qb[0]);
            const uint32_t a2 = __float_as_uint(qb[4]);
            const uint32_t a1 = __float_as_uint(qb[8 * QS]);
            const uint32_t a3 = __float_as_uint(qb[8 * QS + 4]);
            #pragma unroll
            for (int ni = 0; ni < 4; ni++) {
                const float* wb = &sw1[(n0f + 8 * ni + gid) * W1S + k + t4];
                const uint32_t b0 = __float_as_uint(wb[0]);
                const uint32_t b1 = __float_as_uint(wb[4]);
                mma8(hacc[ni], a0, a1, a2, a3, b0, b1);
            }
        }

        // relu + tf32 round + store h chunk to smem
        #pragma unroll
        for (int ni = 0; ni < 4; ni++) {
            const int row = m0 + gid;
            const int col = n0f + 8 * ni + 2 * t4;
            float2 v0;
            v0.x = tf32r(fmaxf(hacc[ni][0], 0.f));
            v0.y = tf32r(fmaxf(hacc[ni][1], 0.f));
            *(float2*)&sh[row * HS + col] = v0;
            float2 v1;
            v1.x = tf32r(fmaxf(hacc[ni][2], 0.f));
            v1.y = tf32r(fmaxf(hacc[ni][3], 0.f));
            *(float2*)&sh[(row + 8) * HS + col] = v1;
        }
        __syncthreads();   // h chunk visible to all warps

        // ---- phase 2: out += h_c @ W2_c^T   (warp tile 16m x 64e) ----
        #pragma unroll
        for (int k = 0; k < CF; k += 8) {
            const float* hb = &sh[(m0 + gid) * HS + k + t4];
            const uint32_t a0 = __float_as_uint(hb[0]);
            const uint32_t a2 = __float_as_uint(hb[4]);
            const uint32_t a1 = __float_as_uint(hb[8 * HS]);
            const uint32_t a3 = __float_as_uint(hb[8 * HS + 4]);
            #pragma unroll
            for (int ni = 0; ni < 8; ni++) {
                const float* wb = &sw2[(n0e + 8 * ni + gid) * W2S + k + t4];
                const uint32_t b0 = __float_as_uint(wb[0]);
                const uint32_t b1 = __float_as_uint(wb[4]);
                mma8(oacc[ni], a0, a1, a2, a3, b0, b1);
            }
        }
        __syncthreads();   // done with h / w tiles before next chunk overwrites
    }

    // ---- epilogue: write out tile (fp32) ----
    float* ob = out + (size_t)blockIdx.x * BM * EDIM;
    #pragma unroll
    for (int ni = 0; ni < 8; ni++) {
        const int row = m0 + gid;
        const int col = n0e + 8 * ni + 2 * t4;
        float2 v0 = make_float2(oacc[ni][0], oacc[ni][1]);
        float2 v1 = make_float2(oacc[ni][2], oacc[ni][3]);
        *(float2*)&ob[row * EDIM + col]       = v0;
        *(float2*)&ob[(row + 8) * EDIM + col] = v1;
    }
}

extern "C" void kernel_launch(void* const* d_in, const int* in_sizes, int n_in,
                              void* d_out, int out_size) {
    const float* x     = (const float*)d_in[0];
    const float* theta = (const float*)d_in[1];
    const float* W1    = (const float*)d_in[2];
    const float* W2    = (const float*)d_in[3];
    float* out = (float*)d_out;

    const int rows = in_sizes[0] / EDIM;   // 131072
    const int grid = rows / BM;            // 1024

    cudaFuncSetAttribute(ffq_kernel, cudaFuncAttributeMaxDynamicSharedMemorySize,
                         SMEM_BYTES);
    ffq_kernel<<<grid, THREADS, SMEM_BYTES>>>(x, theta, W1, W2, out);
}

// round 12
// speedup vs baseline: 1.0030x; 1.0011x over previous
#include <cuda_runtime.h>
#include <cuda_bf16.h>
#include <cstdint>

// out[m,e] = sum_f relu( sum_e' cos(x[m,e'])*cos(theta[e']) * W1[f,e'] ) * W2[e,f]
// M = 131072, E = 128, F = 512.
//
// R6: 512 threads / 16 warps per CTA (was 256/8). Same BM=128 tile, same
// tf32 mma.sync path; warp grid 8m x 2n. Doubles mma issue parallelism at
// unchanged smem footprint (1 CTA/SM), halves register pressure.

#define THREADS 512
#define BM      128
#define EDIM    128
#define FDIM    512
#define CF      64
#define NCHUNK  (FDIM / CF)

// smem row strides in floats (pad +4 -> stride mod 32 == 4 -> conflict-free frags)
#define QS  132
#define HS  68
#define W1S 132
#define W2S 68

#define OFF_Q  0
#define OFF_H  (OFF_Q  + BM * QS)    // 16896
#define OFF_W1 (OFF_H  + BM * HS)    // 25600
#define OFF_W2 (OFF_W1 + CF * W1S)   // 34048
#define OFF_CT (OFF_W2 + EDIM * W2S) // 42752
#define SMEM_FLOATS (OFF_CT + EDIM)  // 42880
#define SMEM_BYTES  (SMEM_FLOATS * 4) // 171520

__device__ __forceinline__ float tf32r(float v) {
    asm("cvt.rna.tf32.f32 %0, %0;" : "+f"(v));
    return v;
}

__device__ __forceinline__ void mma8(float* acc,
                                     uint32_t a0, uint32_t a1, uint32_t a2, uint32_t a3,
                                     uint32_t b0, uint32_t b1) {
    asm volatile(
        "mma.sync.aligned.m16n8k8.row.col.f32.tf32.tf32.f32 "
        "{%0,%1,%2,%3}, {%4,%5,%6,%7}, {%8,%9}, {%0,%1,%2,%3};"
        : "+f"(acc[0]), "+f"(acc[1]), "+f"(acc[2]), "+f"(acc[3])
        : "r"(a0), "r"(a1), "r"(a2), "r"(a3), "r"(b0), "r"(b1));
}

__global__ void __launch_bounds__(THREADS, 1)
ffq_kernel(const float* __restrict__ x,
           const float* __restrict__ theta,
           const float* __restrict__ W1,
           const float* __restrict__ W2,
           float* __restrict__ out) {
    extern __shared__ float s[];
    float* sq  = s + OFF_Q;   // [BM][QS]  q tile (tf32-rounded)
    float* sh  = s + OFF_H;   // [BM][HS]  relu(h) chunk (tf32-rounded)
    float* sw1 = s + OFF_W1;  // [CF][W1S] W1 chunk, rows=f_local, cols=e
    float* sw2 = s + OFF_W2;  // [E][W2S]  W2 chunk, rows=e, cols=f_local
    float* sct = s + OFF_CT;  // [E] cos(theta)

    const int tid  = threadIdx.x;
    const int warp = tid >> 5;
    const int lane = tid & 31;
    const int gid  = lane >> 2;   // group id (0..7)
    const int t4   = lane & 3;    // thread-in-group (0..3)
    const int wm   = warp >> 1;   // 0..7  -> m base (16-row tiles)
    const int wn   = warp & 1;    // 0..1
    const int m0   = 16 * wm;
    const int n0f  = 32 * wn;     // phase-1 f_local base (warp tile 16x32)
    const int n0e  = 64 * wn;     // phase-2 e base       (warp tile 16x64)

    if (tid < EDIM) sct[tid] = cosf(theta[tid]);
    __syncthreads();

    // ---- q tile: load x block, q = cos(x)*cos(theta), round to tf32 ----
    {
        const float4* xg = (const float4*)(x + (size_t)blockIdx.x * (BM * EDIM));
        #pragma unroll
        for (int i = tid; i < BM * EDIM / 4; i += THREADS) {   // 4096 float4
            const int row = i >> 5;         // 32 float4 per row
            const int col = (i & 31) * 4;
            float4 v = xg[i];
            float4 q;
            q.x = tf32r(cosf(v.x) * sct[col + 0]);
            q.y = tf32r(cosf(v.y) * sct[col + 1]);
            q.z = tf32r(cosf(v.z) * sct[col + 2]);
            q.w = tf32r(cosf(v.w) * sct[col + 3]);
            *(float4*)&sq[row * QS + col] = q;
        }
    }

    float oacc[8][4];
    #pragma unroll
    for (int ni = 0; ni < 8; ni++)
        #pragma unroll
        for (int r = 0; r < 4; r++) oacc[ni][r] = 0.f;

    for (int c = 0; c < NCHUNK; c++) {
        // ---- load W1 chunk [CF=64 rows f][128 e] and W2 chunk [128 e][CF f] ----
        {
            const float4* w1g = (const float4*)(W1 + (size_t)c * CF * EDIM);
            #pragma unroll
            for (int i = tid; i < CF * (EDIM / 4); i += THREADS) {  // 2048 float4
                const int r = i >> 5, col = (i & 31) * 4;
                float4 v = w1g[i];
                v.x = tf32r(v.x); v.y = tf32r(v.y); v.z = tf32r(v.z); v.w = tf32r(v.w);
                *(float4*)&sw1[r * W1S + col] = v;
            }
            #pragma unroll
            for (int i = tid; i < EDIM * (CF / 4); i += THREADS) {  // 2048 float4
                const int r = i >> 4, col = (i & 15) * 4;
                float4 v = *(const float4*)(W2 + (size_t)r * FDIM + c * CF + col);
                v.x = tf32r(v.x); v.y = tf32r(v.y); v.z = tf32r(v.z); v.w = tf32r(v.w);
                *(float4*)&sw2[r * W2S + col] = v;
            }
        }
        __syncthreads();   // q + weight tiles ready (also guards prev-iter smem reuse)

        // ---- phase 1: h = q @ W1_c^T   (warp tile 16m x 32f) ----
        float hacc[4][4];
        #pragma unroll
        for (int ni = 0; ni < 4; ni++)
            #pragma unroll
            for (int r = 0; r < 4; r++) hacc[ni][r] = 0.f;

        #pragma unroll
        for (int k = 0; k < EDIM; k += 8) {
            const float* qb = &sq[(m0 + gid) * QS + k + t4];
            const uint32_t a0 = __float_as_uint(qb[0]);
            const uint32_t a2 = __float_as_uint(qb[4]);
            const uint32_t a1 = __float_as_uint(qb[8 * QS]);
            const uint32_t a3 = __float_as_uint(qb[8 * QS + 4]);
            #pragma unroll
            for (int ni = 0; ni < 4; ni++) {
                const float* wb = &sw1[(n0f + 8 * ni + gid) * W1S + k + t4];
                const uint32_t b0 = __float_as_uint(wb[0]);
                const uint32_t b1 = __float_as_uint(wb[4]);
                mma8(hacc[ni], a0, a1, a2, a3, b0, b1);
            }
        }

        // relu + tf32 round + store h chunk to smem
        #pragma unroll
        for (int ni = 0; ni < 4; ni++) {
            const int row = m0 + gid;
            const int col = n0f + 8 * ni + 2 * t4;
            float2 v0;
            v0.x = tf32r(fmaxf(hacc[ni][0], 0.f));
            v0.y = tf32r(fmaxf(hacc[ni][1], 0.f));
            *(float2*)&sh[row * HS + col] = v0;
            float2 v1;
            v1.x = tf32r(fmaxf(hacc[ni][2], 0.f));
            v1.y = tf32r(fmaxf(hacc[ni][3], 0.f));
            *(float2*)&sh[(row + 8) * HS + col] = v1;
        }
        __syncthreads();   // h chunk visible to all warps

        // ---- phase 2: out += h_c @ W2_c^T   (warp tile 16m x 64e) ----
        #pragma unroll
        for (int k = 0; k < CF; k += 8) {
            const float* hb = &sh[(m0 + gid) * HS + k + t4];
            const uint32_t a0 = __float_as_uint(hb[0]);
            const uint32_t a2 = __float_as_uint(hb[4]);
            const uint32_t a1 = __float_as_uint(hb[8 * HS]);
            const uint32_t a3 = __float_as_uint(hb[8 * HS + 4]);
            #pragma unroll
            for (int ni = 0; ni < 8; ni++) {
                const float* wb = &sw2[(n0e + 8 * ni + gid) * W2S + k + t4];
                const uint32_t b0 = __float_as_uint(wb[0]);
                const uint32_t b1 = __float_as_uint(wb[4]);
                mma8(oacc[ni], a0, a1, a2, a3, b0, b1);
            }
        }
        __syncthreads();   // done with h / w tiles before next chunk overwrites
    }

    // ---- epilogue: write out tile (fp32) ----
    float* ob = out + (size_t)blockIdx.x * BM * EDIM;
    #pragma unroll
    for (int ni = 0; ni < 8; ni++) {
        const int row = m0 + gid;
        const int col = n0e + 8 * ni + 2 * t4;
        float2 v0 = make_float2(oacc[ni][0], oacc[ni][1]);
        float2 v1 = make_float2(oacc[ni][2], oacc[ni][3]);
        *(float2*)&ob[row * EDIM + col]       = v0;
        *(float2*)&ob[(row + 8) * EDIM + col] = v1;
    }
}

extern "C" void kernel_launch(void* const* d_in, const int* in_sizes, int n_in,
                              void* d_out, int out_size) {
    const float* x     = (const float*)d_in[0];
    const float* theta = (const float*)d_in[1];
    const float* W1    = (const float*)d_in[2];
    const float* W2    = (const float*)d_in[3];
    float* out = (float*)d_out;

    const int rows = in_sizes[0] / EDIM;   // 131072
    const int grid = rows / BM;            // 1024

    cudaFuncSetAttribute(ffq_kernel, cudaFuncAttributeMaxDynamicSharedMemorySize,
                         SMEM_BYTES);
    ffq_kernel<<<grid, THREADS, SMEM_BYTES>>>(x, theta, W1, W2, out);
}